// round 7
// baseline (speedup 1.0000x reference)
#include <cuda_runtime.h>
#include <cuda_bf16.h>
#include <math.h>
#include <stdint.h>

// Shapes (fixed by the problem)
#define B_ 4
#define T_ 1024
#define C_ 1024
#define H_ 16
#define D_ 64
#define L3C (3 * C_)          // 3072
#define NPOS (2 * T_ - 1)     // 2047

// Scratch (allocation-free rule: __device__ globals)
__device__ float g_qkv[(size_t)B_ * T_ * L3C];   // (B*T, 3C) row-major
__device__ float g_attn[(size_t)B_ * T_ * C_];   // (B*T, C) row-major
__device__ float g_table[NPOS * H_];             // (2L-1, H), pre-scaled by log2(e)

__device__ __forceinline__ uint32_t f2tf32(float x) {
    uint32_t u;
    asm("cvt.rna.tf32.f32 %0, %1;" : "=r"(u) : "f"(x));
    return u;
}
__device__ __forceinline__ float tf32rf(float x) { return __uint_as_float(f2tf32(x)); }

__device__ __forceinline__ float ex2f(float x) {
    float y;
    asm("ex2.approx.f32 %0, %1;" : "=f"(y) : "f"(x));
    return y;
}

__device__ __forceinline__ void mma_tf32(float* d, const uint32_t* a,
                                         uint32_t b0, uint32_t b1) {
    asm volatile(
        "mma.sync.aligned.m16n8k8.row.col.f32.tf32.tf32.f32 "
        "{%0,%1,%2,%3}, {%4,%5,%6,%7}, {%8,%9}, {%0,%1,%2,%3};\n"
        : "+f"(d[0]), "+f"(d[1]), "+f"(d[2]), "+f"(d[3])
        : "r"(a[0]), "r"(a[1]), "r"(a[2]), "r"(a[3]), "r"(b0), "r"(b1));
}

// ---------------------------------------------------------------------------
// Kernel 1: reduce rel_pos_emb (2047,1024) -> table (2047,16), × log2(e)
// ---------------------------------------------------------------------------
__global__ __launch_bounds__(512) void reduce_table_kernel(const float* __restrict__ rel) {
    int row = blockIdx.x;
    int w   = threadIdx.x >> 5;
    int lane = threadIdx.x & 31;
    const float* p = rel + (size_t)row * C_ + w * D_;
    float s = p[lane] + p[lane + 32];
    #pragma unroll
    for (int off = 16; off > 0; off >>= 1)
        s += __shfl_xor_sync(0xffffffffu, s, off);
    if (lane == 0) g_table[row * H_ + w] = s * 1.4426950408889634f;
}

// ---------------------------------------------------------------------------
// Kernel 2: TF32 tensor-core GEMM  C[M,N] = A[M,K] @ Bmat[N,K]^T + bias[N]
// (unchanged from R5)
// ---------------------------------------------------------------------------
#define TBM 128
#define TBN 128
#define TBK 16
#define TST 136

__global__ __launch_bounds__(256, 2) void gemm_tf32_nt_bias(
    const float* __restrict__ A, const float* __restrict__ Bm,
    const float* __restrict__ bias, float* __restrict__ Cout,
    int M, int N, int K)
{
    __shared__ float As[2][TBK][TST];
    __shared__ float Bs[2][TBK][TST];

    const int tid  = threadIdx.x;
    const int lane = tid & 31;
    const int wid  = tid >> 5;
    const int wm   = (wid & 3) * 32;
    const int wn   = (wid >> 2) * 64;
    const int m0   = blockIdx.y * TBM;
    const int n0   = blockIdx.x * TBN;

    const int qr = lane >> 2;
    const int qc = lane & 3;

    const int lr = tid & 127;
    const int lh = tid >> 7;

    const float* Aptr = A  + (size_t)(m0 + lr) * K + lh * 8;
    const float* Bptr = Bm + (size_t)(n0 + lr) * K + lh * 8;

    float acc[2][8][4];
    #pragma unroll
    for (int i = 0; i < 2; i++)
        #pragma unroll
        for (int j = 0; j < 8; j++)
            #pragma unroll
            for (int r = 0; r < 4; r++) acc[i][j][r] = 0.f;

    float4 fa[2], fb[2];
    #pragma unroll
    for (int j = 0; j < 2; j++) {
        fa[j] = *(const float4*)(Aptr + j * 4);
        fb[j] = *(const float4*)(Bptr + j * 4);
    }
    #pragma unroll
    for (int j = 0; j < 2; j++) {
        int kk = lh * 8 + j * 4;
        As[0][kk + 0][lr] = tf32rf(fa[j].x);
        As[0][kk + 1][lr] = tf32rf(fa[j].y);
        As[0][kk + 2][lr] = tf32rf(fa[j].z);
        As[0][kk + 3][lr] = tf32rf(fa[j].w);
        Bs[0][kk + 0][lr] = tf32rf(fb[j].x);
        Bs[0][kk + 1][lr] = tf32rf(fb[j].y);
        Bs[0][kk + 2][lr] = tf32rf(fb[j].z);
        Bs[0][kk + 3][lr] = tf32rf(fb[j].w);
    }
    __syncthreads();

    const int nIter = K / TBK;
    for (int t = 0; t < nIter; t++) {
        const int buf = t & 1;
        if (t + 1 < nIter) {
            const float* ap = Aptr + (t + 1) * TBK;
            const float* bp = Bptr + (t + 1) * TBK;
            #pragma unroll
            for (int j = 0; j < 2; j++) {
                fa[j] = *(const float4*)(ap + j * 4);
                fb[j] = *(const float4*)(bp + j * 4);
            }
        }

        #pragma unroll
        for (int ks = 0; ks < 2; ks++) {
            const int kb = ks * 8;
            uint32_t af[2][4];
            #pragma unroll
            for (int ms = 0; ms < 2; ms++) {
                int r = wm + ms * 16 + qr;
                af[ms][0] = __float_as_uint(As[buf][kb + qc][r]);
                af[ms][1] = __float_as_uint(As[buf][kb + qc][r + 8]);
                af[ms][2] = __float_as_uint(As[buf][kb + qc + 4][r]);
                af[ms][3] = __float_as_uint(As[buf][kb + qc + 4][r + 8]);
            }
            #pragma unroll
            for (int ns = 0; ns < 8; ns++) {
                int c = wn + ns * 8 + qr;
                uint32_t b0 = __float_as_uint(Bs[buf][kb + qc][c]);
                uint32_t b1 = __float_as_uint(Bs[buf][kb + qc + 4][c]);
                mma_tf32(acc[0][ns], af[0], b0, b1);
                mma_tf32(acc[1][ns], af[1], b0, b1);
            }
        }

        if (t + 1 < nIter) {
            const int nb = buf ^ 1;
            #pragma unroll
            for (int j = 0; j < 2; j++) {
                int kk = lh * 8 + j * 4;
                As[nb][kk + 0][lr] = tf32rf(fa[j].x);
                As[nb][kk + 1][lr] = tf32rf(fa[j].y);
                As[nb][kk + 2][lr] = tf32rf(fa[j].z);
                As[nb][kk + 3][lr] = tf32rf(fa[j].w);
                Bs[nb][kk + 0][lr] = tf32rf(fb[j].x);
                Bs[nb][kk + 1][lr] = tf32rf(fb[j].y);
                Bs[nb][kk + 2][lr] = tf32rf(fb[j].z);
                Bs[nb][kk + 3][lr] = tf32rf(fb[j].w);
            }
        }
        __syncthreads();
    }

    #pragma unroll
    for (int ms = 0; ms < 2; ms++) {
        int r = m0 + wm + ms * 16 + qr;
        #pragma unroll
        for (int ns = 0; ns < 8; ns++) {
            int c = n0 + wn + ns * 8 + qc * 2;
            float b0 = bias[c], b1 = bias[c + 1];
            float2 v0 = make_float2(acc[ms][ns][0] + b0, acc[ms][ns][1] + b1);
            float2 v1 = make_float2(acc[ms][ns][2] + b0, acc[ms][ns][3] + b1);
            *(float2*)&Cout[(size_t)r * N + c]       = v0;
            *(float2*)&Cout[(size_t)(r + 8) * N + c] = v1;
        }
    }
}

// ---------------------------------------------------------------------------
// Kernel 3: TF32 MMA flash attention, log2-domain softmax, rel-pos bias,
// causal mask. Grid: (T/128, B*H). 256 threads, 8 warps x 16 query rows.
// All smem tiles natural row-major, stride 72 (conflict-free frag LDS).
// ---------------------------------------------------------------------------
#define FBM 128
#define FBN 64
#define FST 72
#define FOFF_K 0
#define FOFF_V (64 * FST)               // 4608
#define FOFF_Q (2 * 64 * FST)           // 9216
#define FOFF_P (FOFF_Q + 128 * FST)     // 18432
#define FOFF_B (FOFF_P + 128 * FST)     // 27648
#define FLASH_SMEM_FLOATS (FOFF_B + 192)

__global__ __launch_bounds__(256) void flash_mma_kernel(float* __restrict__ out) {
    extern __shared__ float sm[];
    float* Ks = sm + FOFF_K;   // [key=64][d=64] stride FST
    float* Vs = sm + FOFF_V;   // [key=64][d=64]
    float* Qs = sm + FOFF_Q;   // [row=128][d=64]
    float* Ps = sm + FOFF_P;   // [row=128][key=64], per-warp 16-row slices
    float* sb = sm + FOFF_B;   // 191 bias values

    const int bh = blockIdx.y;
    const int b  = bh >> 4;
    const int h  = bh & 15;
    const int m0 = blockIdx.x * FBM;

    const int tid = threadIdx.x;
    const int lane = tid & 31;
    const int wid  = tid >> 5;
    const int qr = lane >> 2;
    const int qc = lane & 3;
    const int wm = wid * 16;
    float* Pw = Ps + wm * FST;

    // stage Q, scaled by (1/8)*log2(e), tf32-rounded
    {
        const float qsc = 0.125f * 1.4426950408889634f;
        const float* qb = g_qkv + (size_t)(b * T_ + m0) * L3C + h * D_;
        #pragma unroll
        for (int i = 0; i < 8; i++) {
            int f = tid + i * 256;
            int row = f >> 4, c4 = (f & 15) * 4;
            float4 v = *(const float4*)(qb + (size_t)row * L3C + c4);
            float* d = &Qs[row * FST + c4];
            d[0] = tf32rf(v.x * qsc);
            d[1] = tf32rf(v.y * qsc);
            d[2] = tf32rf(v.z * qsc);
            d[3] = tf32rf(v.w * qsc);
        }
    }

    float m_i[2] = {-1e30f, -1e30f};
    float l_i[2] = {0.f, 0.f};
    float o[8][4];
    #pragma unroll
    for (int ns = 0; ns < 8; ns++)
        #pragma unroll
        for (int r = 0; r < 4; r++) o[ns][r] = 0.f;

    const int ntiles = 2 * blockIdx.x + 2;
    for (int t = 0; t < ntiles; t++) {
        const int j0 = t * FBN;
        // load K, V tiles (tf32-rounded)
        {
            const float* kb_ = g_qkv + (size_t)(b * T_ + j0) * L3C + C_ + h * D_;
            const float* vb_ = kb_ + C_;
            #pragma unroll
            for (int i = 0; i < 4; i++) {
                int f = tid + i * 256;
                int row = f >> 4, c4 = (f & 15) * 4;
                float4 kv = *(const float4*)(kb_ + (size_t)row * L3C + c4);
                float4 vv = *(const float4*)(vb_ + (size_t)row * L3C + c4);
                float* dk = &Ks[row * FST + c4];
                dk[0] = tf32rf(kv.x); dk[1] = tf32rf(kv.y);
                dk[2] = tf32rf(kv.z); dk[3] = tf32rf(kv.w);
                float* dv = &Vs[row * FST + c4];
                dv[0] = tf32rf(vv.x); dv[1] = tf32rf(vv.y);
                dv[2] = tf32rf(vv.z); dv[3] = tf32rf(vv.w);
            }
            if (tid < 191) sb[tid] = g_table[(m0 - j0 + 960 + tid) * H_ + h];
        }
        __syncthreads();

        const int rel = j0 - m0;
        if (rel <= wm + 15) {   // warp not fully masked
            // S = Q @ K^T  (log2 domain, bias pre-scaled)
            float sacc[8][4];
            #pragma unroll
            for (int ns = 0; ns < 8; ns++)
                #pragma unroll
                for (int r = 0; r < 4; r++) sacc[ns][r] = 0.f;

            #pragma unroll
            for (int kb = 0; kb < 8; kb++) {
                uint32_t a[4];
                a[0] = __float_as_uint(Qs[(wm + qr) * FST + kb * 8 + qc]);
                a[1] = __float_as_uint(Qs[(wm + qr + 8) * FST + kb * 8 + qc]);
                a[2] = __float_as_uint(Qs[(wm + qr) * FST + kb * 8 + qc + 4]);
                a[3] = __float_as_uint(Qs[(wm + qr + 8) * FST + kb * 8 + qc + 4]);
                #pragma unroll
                for (int ns = 0; ns < 8; ns++) {
                    uint32_t b0 = __float_as_uint(Ks[(ns * 8 + qr) * FST + kb * 8 + qc]);
                    uint32_t b1 = __float_as_uint(Ks[(ns * 8 + qr) * FST + kb * 8 + qc + 4]);
                    mma_tf32(sacc[ns], a, b0, b1);
                }
            }

            const bool tail = (rel >= 0);
            #pragma unroll
            for (int hl = 0; hl < 2; hl++) {
                const int rloc = wm + qr + hl * 8;
                float mx = -1e30f;
                #pragma unroll
                for (int ns = 0; ns < 8; ns++) {
                    #pragma unroll
                    for (int j2 = 0; j2 < 2; j2++) {
                        int col = ns * 8 + qc * 2 + j2;
                        float v = sacc[ns][hl * 2 + j2] + sb[rloc - col + 63];
                        if (tail && col + rel > rloc) v = -1e30f;
                        sacc[ns][hl * 2 + j2] = v;
                        mx = fmaxf(mx, v);
                    }
                }
                mx = fmaxf(mx, __shfl_xor_sync(0xffffffffu, mx, 1));
                mx = fmaxf(mx, __shfl_xor_sync(0xffffffffu, mx, 2));
                float mnew = fmaxf(m_i[hl], mx);
                float corr = ex2f(m_i[hl] - mnew);
                float rs = 0.f;
                #pragma unroll
                for (int ns = 0; ns < 8; ns++) {
                    #pragma unroll
                    for (int j2 = 0; j2 < 2; j2++) {
                        float p = ex2f(sacc[ns][hl * 2 + j2] - mnew);
                        sacc[ns][hl * 2 + j2] = p;
                        rs += p;
                    }
                }
                rs += __shfl_xor_sync(0xffffffffu, rs, 1);
                rs += __shfl_xor_sync(0xffffffffu, rs, 2);
                l_i[hl] = l_i[hl] * corr + rs;
                m_i[hl] = mnew;
                #pragma unroll
                for (int ns = 0; ns < 8; ns++) {
                    o[ns][hl * 2 + 0] *= corr;
                    o[ns][hl * 2 + 1] *= corr;
                }
            }

            // stage P (tf32-rounded) into per-warp smem slice
            #pragma unroll
            for (int ns = 0; ns < 8; ns++) {
                float2 p0 = make_float2(tf32rf(sacc[ns][0]), tf32rf(sacc[ns][1]));
                float2 p1 = make_float2(tf32rf(sacc[ns][2]), tf32rf(sacc[ns][3]));
                *(float2*)&Pw[qr * FST + ns * 8 + qc * 2] = p0;
                *(float2*)&Pw[(qr + 8) * FST + ns * 8 + qc * 2] = p1;
            }
            __syncwarp();

            // O += P @ V
            #pragma unroll
            for (int kb = 0; kb < 8; kb++) {
                uint32_t a[4];
                a[0] = __float_as_uint(Pw[qr * FST + kb * 8 + qc]);
                a[1] = __float_as_uint(Pw[(qr + 8) * FST + kb * 8 + qc]);
                a[2] = __float_as_uint(Pw[qr * FST + kb * 8 + qc + 4]);
                a[3] = __float_as_uint(Pw[(qr + 8) * FST + kb * 8 + qc + 4]);
                #pragma unroll
                for (int ns = 0; ns < 8; ns++) {
                    uint32_t b0 = __float_as_uint(Vs[(kb * 8 + qc) * FST + ns * 8 + qr]);
                    uint32_t b1 = __float_as_uint(Vs[(kb * 8 + qc + 4) * FST + ns * 8 + qr]);
                    mma_tf32(o[ns], a, b0, b1);
                }
            }
        }
        __syncthreads();
    }

    // epilogue: normalize, write (B,T,H*D)
    #pragma unroll
    for (int hl = 0; hl < 2; hl++) {
        float inv = 1.f / l_i[hl];
        int rg = m0 + wm + qr + hl * 8;
        float* ob = out + (size_t)(b * T_ + rg) * C_ + h * D_;
        #pragma unroll
        for (int ns = 0; ns < 8; ns++) {
            float2 w = make_float2(o[ns][hl * 2 + 0] * inv, o[ns][hl * 2 + 1] * inv);
            *(float2*)&ob[ns * 8 + qc * 2] = w;
        }
    }
}

// ---------------------------------------------------------------------------
extern "C" void kernel_launch(void* const* d_in, const int* in_sizes, int n_in,
                              void* d_out, int out_size) {
    const float* x      = (const float*)d_in[0];
    const float* qkv_w  = (const float*)d_in[1];
    const float* qkv_b  = (const float*)d_in[2];
    const float* proj_w = (const float*)d_in[3];
    const float* proj_b = (const float*)d_in[4];
    const float* rel    = (const float*)d_in[5];
    float* out = (float*)d_out;

    float *p_qkv, *p_attn;
    cudaGetSymbolAddress((void**)&p_qkv, g_qkv);
    cudaGetSymbolAddress((void**)&p_attn, g_attn);

    // 1) bias table reduce (scaled by log2 e)
    reduce_table_kernel<<<NPOS, 512>>>(rel);

    // 2) QKV projection (tf32 MMA)
    {
        dim3 grid(L3C / TBN, (B_ * T_) / TBM);
        gemm_tf32_nt_bias<<<grid, 256>>>(x, qkv_w, qkv_b, p_qkv, B_ * T_, L3C, C_);
    }

    // 3) fused flash attention (tf32 MMA)
    {
        static int smem_set = 0;
        size_t smem = FLASH_SMEM_FLOATS * sizeof(float);
        if (!smem_set) {
            cudaFuncSetAttribute(flash_mma_kernel,
                                 cudaFuncAttributeMaxDynamicSharedMemorySize, (int)smem);
            smem_set = 1;
        }
        dim3 grid(T_ / FBM, B_ * H_);
        flash_mma_kernel<<<grid, 256, smem>>>(p_attn);
    }

    // 4) output projection (tf32 MMA)
    {
        dim3 grid(C_ / TBN, (B_ * T_) / TBM);
        gemm_tf32_nt_bias<<<grid, 256>>>(p_attn, proj_w, proj_b, out, B_ * T_, C_, C_);
    }
}

// round 8
// speedup vs baseline: 1.3755x; 1.3755x over previous
#include <cuda_runtime.h>
#include <cuda_bf16.h>
#include <math.h>
#include <stdint.h>

// Shapes (fixed by the problem)
#define B_ 4
#define T_ 1024
#define C_ 1024
#define H_ 16
#define D_ 64
#define L3C (3 * C_)          // 3072
#define NPOS (2 * T_ - 1)     // 2047

// Scratch (allocation-free rule: __device__ globals)
__device__ float g_qkv[(size_t)B_ * T_ * L3C];   // (B*T, 3C) row-major
__device__ float g_attn[(size_t)B_ * T_ * C_];   // (B*T, C) row-major
__device__ float g_table[NPOS * H_];             // (2L-1, H)

__device__ __forceinline__ uint32_t f2tf32(float x) {
    uint32_t u;
    asm("cvt.rna.tf32.f32 %0, %1;" : "=r"(u) : "f"(x));
    return u;
}
__device__ __forceinline__ float tf32rf(float x) { return __uint_as_float(f2tf32(x)); }

__device__ __forceinline__ void mma_tf32(float* d, const uint32_t* a,
                                         uint32_t b0, uint32_t b1) {
    asm volatile(
        "mma.sync.aligned.m16n8k8.row.col.f32.tf32.tf32.f32 "
        "{%0,%1,%2,%3}, {%4,%5,%6,%7}, {%8,%9}, {%0,%1,%2,%3};\n"
        : "+f"(d[0]), "+f"(d[1]), "+f"(d[2]), "+f"(d[3])
        : "r"(a[0]), "r"(a[1]), "r"(a[2]), "r"(a[3]), "r"(b0), "r"(b1));
}

__device__ __forceinline__ void ldsm4(uint32_t* r, uint32_t saddr) {
    asm volatile(
        "ldmatrix.sync.aligned.m8n8.x4.shared.b16 {%0,%1,%2,%3}, [%4];\n"
        : "=r"(r[0]), "=r"(r[1]), "=r"(r[2]), "=r"(r[3]) : "r"(saddr));
}

// ---------------------------------------------------------------------------
// Kernel 1: reduce rel_pos_emb (2047,1024) -> table (2047,16) summing over D
// (R5 version: NO log2e scaling)
// ---------------------------------------------------------------------------
__global__ __launch_bounds__(512) void reduce_table_kernel(const float* __restrict__ rel) {
    int row = blockIdx.x;
    int w   = threadIdx.x >> 5;
    int lane = threadIdx.x & 31;
    const float* p = rel + (size_t)row * C_ + w * D_;
    float s = p[lane] + p[lane + 32];
    #pragma unroll
    for (int off = 16; off > 0; off >>= 1)
        s += __shfl_xor_sync(0xffffffffu, s, off);
    if (lane == 0) g_table[row * H_ + w] = s;
}

// ---------------------------------------------------------------------------
// Kernel 2: TF32 tensor-core GEMM  C[M,N] = A[M,K] @ Bmat[N,K]^T + bias[N]
// 128x128x16 tile, 256 threads, 8 warps (4m x 2n), warp tile 32x64.
// smem [row][k] with stride 20 floats (80B: ldmatrix + STS conflict-free).
// Fragments loaded via ldmatrix.m8n8.x4.b16 (bit-exact for tf32).
// ---------------------------------------------------------------------------
#define TBM 128
#define TBN 128
#define TBK 16
#define GST 20                         // padded floats per row
#define GBUF (TBM * GST)               // floats per buffer per operand

__global__ __launch_bounds__(256, 2) void gemm_tf32_nt_bias(
    const float* __restrict__ A, const float* __restrict__ Bm,
    const float* __restrict__ bias, float* __restrict__ Cout,
    int M, int N, int K)
{
    __shared__ float As[2][TBM][GST];
    __shared__ float Bs[2][TBN][GST];

    const int tid  = threadIdx.x;
    const int lane = tid & 31;
    const int wid  = tid >> 5;
    const int wm   = (wid & 3) * 32;
    const int wn   = (wid >> 2) * 64;
    const int m0   = blockIdx.y * TBM;
    const int n0   = blockIdx.x * TBN;

    const int qr = lane >> 2;
    const int qc = lane & 3;

    const int lr = tid & 127;
    const int lh = tid >> 7;

    const float* Aptr = A  + (size_t)(m0 + lr) * K + lh * 8;
    const float* Bptr = Bm + (size_t)(n0 + lr) * K + lh * 8;

    // ldmatrix per-lane base addresses (bytes, shared space)
    const uint32_t baseA = (uint32_t)__cvta_generic_to_shared(&As[0][0][0]);
    const uint32_t baseB = (uint32_t)__cvta_generic_to_shared(&Bs[0][0][0]);
    // A x4: mat0 rows 0-7 col16 0 | mat1 rows 8-15 col16 0 | mat2 rows 0-7 col16 1 | mat3 rows 8-15 col16 1
    const uint32_t aAddr = baseA + (((wm + (lane & 15)) * GST + (lane >> 4) * 4) << 2);
    // B x4 per group g: mat0 rows 16g+0-7 c0 | mat1 rows 16g+0-7 c1 | mat2 rows +8 c0 | mat3 rows +8 c1
    uint32_t bAddr[4];
    #pragma unroll
    for (int g = 0; g < 4; g++)
        bAddr[g] = baseB + (((wn + 16 * g + (lane & 7) + ((lane >> 4) & 1) * 8) * GST
                             + ((lane >> 3) & 1) * 4) << 2);

    float acc[2][8][4];
    #pragma unroll
    for (int i = 0; i < 2; i++)
        #pragma unroll
        for (int j = 0; j < 8; j++)
            #pragma unroll
            for (int r = 0; r < 4; r++) acc[i][j][r] = 0.f;

    float4 fa[2], fb[2];
    #pragma unroll
    for (int j = 0; j < 2; j++) {
        fa[j] = *(const float4*)(Aptr + j * 4);
        fb[j] = *(const float4*)(Bptr + j * 4);
    }
    #pragma unroll
    for (int j = 0; j < 2; j++) {
        float* da = &As[0][lr][lh * 8 + j * 4];
        da[0] = tf32rf(fa[j].x); da[1] = tf32rf(fa[j].y);
        da[2] = tf32rf(fa[j].z); da[3] = tf32rf(fa[j].w);
        float* db = &Bs[0][lr][lh * 8 + j * 4];
        db[0] = tf32rf(fb[j].x); db[1] = tf32rf(fb[j].y);
        db[2] = tf32rf(fb[j].z); db[3] = tf32rf(fb[j].w);
    }
    __syncthreads();

    const int nIter = K / TBK;
    for (int t = 0; t < nIter; t++) {
        const int buf = t & 1;
        const uint32_t bo = (uint32_t)buf * (GBUF * 4);
        if (t + 1 < nIter) {
            const float* ap = Aptr + (t + 1) * TBK;
            const float* bp = Bptr + (t + 1) * TBK;
            #pragma unroll
            for (int j = 0; j < 2; j++) {
                fa[j] = *(const float4*)(ap + j * 4);
                fb[j] = *(const float4*)(bp + j * 4);
            }
        }

        #pragma unroll
        for (int ks = 0; ks < 2; ks++) {
            const uint32_t ko = bo + ks * 32;   // ks*8 floats = 32 bytes
            uint32_t af0[4], af1[4], bf[4][4];
            ldsm4(af0, aAddr + ko);
            ldsm4(af1, aAddr + (16 * GST * 4) + ko);
            #pragma unroll
            for (int g = 0; g < 4; g++) ldsm4(bf[g], bAddr[g] + ko);
            #pragma unroll
            for (int g = 0; g < 4; g++) {
                mma_tf32(acc[0][2 * g],     af0, bf[g][0], bf[g][1]);
                mma_tf32(acc[0][2 * g + 1], af0, bf[g][2], bf[g][3]);
                mma_tf32(acc[1][2 * g],     af1, bf[g][0], bf[g][1]);
                mma_tf32(acc[1][2 * g + 1], af1, bf[g][2], bf[g][3]);
            }
        }

        if (t + 1 < nIter) {
            const int nb = buf ^ 1;
            #pragma unroll
            for (int j = 0; j < 2; j++) {
                float* da = &As[nb][lr][lh * 8 + j * 4];
                da[0] = tf32rf(fa[j].x); da[1] = tf32rf(fa[j].y);
                da[2] = tf32rf(fa[j].z); da[3] = tf32rf(fa[j].w);
                float* db = &Bs[nb][lr][lh * 8 + j * 4];
                db[0] = tf32rf(fb[j].x); db[1] = tf32rf(fb[j].y);
                db[2] = tf32rf(fb[j].z); db[3] = tf32rf(fb[j].w);
            }
        }
        __syncthreads();
    }

    // epilogue: + bias, write (float2 stores)
    #pragma unroll
    for (int ms = 0; ms < 2; ms++) {
        int r = m0 + wm + ms * 16 + qr;
        #pragma unroll
        for (int ns = 0; ns < 8; ns++) {
            int c = n0 + wn + ns * 8 + qc * 2;
            float b0 = bias[c], b1 = bias[c + 1];
            float2 v0 = make_float2(acc[ms][ns][0] + b0, acc[ms][ns][1] + b1);
            float2 v1 = make_float2(acc[ms][ns][2] + b0, acc[ms][ns][3] + b1);
            *(float2*)&Cout[(size_t)r * N + c]       = v0;
            *(float2*)&Cout[(size_t)(r + 8) * N + c] = v1;
        }
    }
}

// ---------------------------------------------------------------------------
// Kernel 3: fused flash attention with rel-pos bias + causal mask.
// (R5 scalar version — known good at ~315us)
// Grid: (T/64, B*H). Block: 256 threads (16x16), each thread 4x4.
// ---------------------------------------------------------------------------
#define QST_STRIDE 68
#define PS_STRIDE 65
#define OFF_QST 0
#define OFF_KST (OFF_QST + 64 * QST_STRIDE)
#define OFF_VS  (OFF_KST + 64 * QST_STRIDE)
#define OFF_PS  (OFF_VS + 64 * 64)
#define OFF_SB  (OFF_PS + 64 * PS_STRIDE)
#define FLASH_SMEM_FLOATS (OFF_SB + 128)

__global__ __launch_bounds__(256) void flash_attn_kernel(float* __restrict__ out) {
    extern __shared__ float sm[];
    float* Qst   = sm + OFF_QST;
    float* Kst   = sm + OFF_KST;
    float* Vs    = sm + OFF_VS;
    float* Ps    = sm + OFF_PS;
    float* sbias = sm + OFF_SB;

    const int bh = blockIdx.y;
    const int b  = bh >> 4;
    const int h  = bh & 15;
    const int m0 = blockIdx.x * 64;

    const int tid = threadIdx.x;
    const int tx = tid & 15;
    const int ty = tid >> 4;
    const int lrow = tid >> 2;
    const int lcol = (tid & 3) * 4;

    {
        const float sc = 0.125f;
        const float* qp = g_qkv + (size_t)(b * T_ + m0 + lrow) * L3C + h * D_;
        #pragma unroll
        for (int c = 0; c < 4; c++) {
            int col = lcol + c * 16;
            float4 v = *(const float4*)(qp + col);
            Qst[(col + 0) * QST_STRIDE + lrow] = v.x * sc;
            Qst[(col + 1) * QST_STRIDE + lrow] = v.y * sc;
            Qst[(col + 2) * QST_STRIDE + lrow] = v.z * sc;
            Qst[(col + 3) * QST_STRIDE + lrow] = v.w * sc;
        }
    }

    float m_i[4], l_i[4], o[4][4];
    #pragma unroll
    for (int i = 0; i < 4; i++) {
        m_i[i] = -1e30f; l_i[i] = 0.f;
        #pragma unroll
        for (int j = 0; j < 4; j++) o[i][j] = 0.f;
    }

    const int ntiles = blockIdx.x + 1;
    for (int t = 0; t < ntiles; t++) {
        const int j0 = t * 64;
        {
            const float* kp = g_qkv + (size_t)(b * T_ + j0 + lrow) * L3C + C_ + h * D_;
            const float* vp = g_qkv + (size_t)(b * T_ + j0 + lrow) * L3C + 2 * C_ + h * D_;
            #pragma unroll
            for (int c = 0; c < 4; c++) {
                int col = lcol + c * 16;
                float4 v = *(const float4*)(kp + col);
                Kst[(col + 0) * QST_STRIDE + lrow] = v.x;
                Kst[(col + 1) * QST_STRIDE + lrow] = v.y;
                Kst[(col + 2) * QST_STRIDE + lrow] = v.z;
                Kst[(col + 3) * QST_STRIDE + lrow] = v.w;
                *(float4*)&Vs[lrow * 64 + col] = *(const float4*)(vp + col);
            }
        }
        if (tid < 127) {
            sbias[tid] = g_table[(m0 - j0 + 960 + tid) * H_ + h];
        }
        __syncthreads();

        float s[4][4];
        #pragma unroll
        for (int i = 0; i < 4; i++)
            #pragma unroll
            for (int j = 0; j < 4; j++) s[i][j] = 0.f;
        #pragma unroll 8
        for (int d = 0; d < 64; d++) {
            float4 a4 = *(const float4*)&Qst[d * QST_STRIDE + ty * 4];
            float4 b4 = *(const float4*)&Kst[d * QST_STRIDE + tx * 4];
            float a[4] = {a4.x, a4.y, a4.z, a4.w};
            float bb[4] = {b4.x, b4.y, b4.z, b4.w};
            #pragma unroll
            for (int i = 0; i < 4; i++)
                #pragma unroll
                for (int j = 0; j < 4; j++)
                    s[i][j] = fmaf(a[i], bb[j], s[i][j]);
        }
        const bool diag = (t == blockIdx.x);
        #pragma unroll
        for (int i = 0; i < 4; i++) {
            int row = ty * 4 + i;
            #pragma unroll
            for (int j = 0; j < 4; j++) {
                int col = tx * 4 + j;
                s[i][j] += sbias[row - col + 63];
                if (diag && col > row) s[i][j] = -1e30f;
            }
        }
        #pragma unroll
        for (int i = 0; i < 4; i++) {
            float mx = s[i][0];
            mx = fmaxf(mx, s[i][1]); mx = fmaxf(mx, s[i][2]); mx = fmaxf(mx, s[i][3]);
            #pragma unroll
            for (int off = 8; off > 0; off >>= 1)
                mx = fmaxf(mx, __shfl_xor_sync(0xffffffffu, mx, off));
            float mnew = fmaxf(m_i[i], mx);
            float corr = __expf(m_i[i] - mnew);
            float rs = 0.f;
            #pragma unroll
            for (int j = 0; j < 4; j++) {
                s[i][j] = __expf(s[i][j] - mnew);
                rs += s[i][j];
            }
            #pragma unroll
            for (int off = 8; off > 0; off >>= 1)
                rs += __shfl_xor_sync(0xffffffffu, rs, off);
            l_i[i] = l_i[i] * corr + rs;
            #pragma unroll
            for (int j = 0; j < 4; j++) o[i][j] *= corr;
            m_i[i] = mnew;
            int row = ty * 4 + i;
            #pragma unroll
            for (int j = 0; j < 4; j++)
                Ps[row * PS_STRIDE + tx * 4 + j] = s[i][j];
        }
        __syncthreads();

        #pragma unroll 4
        for (int sI = 0; sI < 64; sI++) {
            float4 b4 = *(const float4*)&Vs[sI * 64 + tx * 4];
            float bb[4] = {b4.x, b4.y, b4.z, b4.w};
            float a0 = Ps[(ty * 4 + 0) * PS_STRIDE + sI];
            float a1 = Ps[(ty * 4 + 1) * PS_STRIDE + sI];
            float a2 = Ps[(ty * 4 + 2) * PS_STRIDE + sI];
            float a3 = Ps[(ty * 4 + 3) * PS_STRIDE + sI];
            #pragma unroll
            for (int j = 0; j < 4; j++) {
                o[0][j] = fmaf(a0, bb[j], o[0][j]);
                o[1][j] = fmaf(a1, bb[j], o[1][j]);
                o[2][j] = fmaf(a2, bb[j], o[2][j]);
                o[3][j] = fmaf(a3, bb[j], o[3][j]);
            }
        }
        __syncthreads();
    }

    #pragma unroll
    for (int i = 0; i < 4; i++) {
        float inv = 1.f / l_i[i];
        int row = m0 + ty * 4 + i;
        float4 r;
        r.x = o[i][0] * inv; r.y = o[i][1] * inv;
        r.z = o[i][2] * inv; r.w = o[i][3] * inv;
        *(float4*)&out[(size_t)(b * T_ + row) * C_ + h * D_ + tx * 4] = r;
    }
}

// ---------------------------------------------------------------------------
extern "C" void kernel_launch(void* const* d_in, const int* in_sizes, int n_in,
                              void* d_out, int out_size) {
    const float* x      = (const float*)d_in[0];
    const float* qkv_w  = (const float*)d_in[1];
    const float* qkv_b  = (const float*)d_in[2];
    const float* proj_w = (const float*)d_in[3];
    const float* proj_b = (const float*)d_in[4];
    const float* rel    = (const float*)d_in[5];
    float* out = (float*)d_out;

    float *p_qkv, *p_attn;
    cudaGetSymbolAddress((void**)&p_qkv, g_qkv);
    cudaGetSymbolAddress((void**)&p_attn, g_attn);

    // 1) bias table reduce
    reduce_table_kernel<<<NPOS, 512>>>(rel);

    // 2) QKV projection (tf32 MMA + ldmatrix)
    {
        dim3 grid(L3C / TBN, (B_ * T_) / TBM);
        gemm_tf32_nt_bias<<<grid, 256>>>(x, qkv_w, qkv_b, p_qkv, B_ * T_, L3C, C_);
    }

    // 3) fused flash attention (scalar, known good)
    {
        static int smem_set = 0;
        size_t smem = FLASH_SMEM_FLOATS * sizeof(float);
        if (!smem_set) {
            cudaFuncSetAttribute(flash_attn_kernel,
                                 cudaFuncAttributeMaxDynamicSharedMemorySize, (int)smem);
            smem_set = 1;
        }
        dim3 grid(T_ / 64, B_ * H_);
        flash_attn_kernel<<<grid, 256, smem>>>(p_attn);
    }

    // 4) output projection (tf32 MMA + ldmatrix)
    {
        dim3 grid(C_ / TBN, (B_ * T_) / TBM);
        gemm_tf32_nt_bias<<<grid, 256>>>(p_attn, proj_w, proj_b, out, B_ * T_, C_, C_);
    }
}

// round 9
// speedup vs baseline: 1.9669x; 1.4300x over previous
#include <cuda_runtime.h>
#include <cuda_bf16.h>
#include <math.h>
#include <stdint.h>

// Shapes (fixed by the problem)
#define B_ 4
#define T_ 1024
#define C_ 1024
#define H_ 16
#define D_ 64
#define L3C (3 * C_)          // 3072
#define NPOS (2 * T_ - 1)     // 2047

// Scratch (allocation-free rule: __device__ globals)
__device__ float g_qkv[(size_t)B_ * T_ * L3C];   // (B*T, 3C) row-major
__device__ float g_attn[(size_t)B_ * T_ * C_];   // (B*T, C) row-major
__device__ float g_table[NPOS * H_];             // (2L-1, H), pre-scaled by log2(e)

__device__ __forceinline__ uint32_t f2tf32(float x) {
    uint32_t u;
    asm("cvt.rna.tf32.f32 %0, %1;" : "=r"(u) : "f"(x));
    return u;
}
__device__ __forceinline__ float tf32rf(float x) { return __uint_as_float(f2tf32(x)); }

__device__ __forceinline__ float ex2f(float x) {
    float y;
    asm("ex2.approx.f32 %0, %1;" : "=f"(y) : "f"(x));
    return y;
}

__device__ __forceinline__ void mma_tf32(float* d, const uint32_t* a,
                                         uint32_t b0, uint32_t b1) {
    asm volatile(
        "mma.sync.aligned.m16n8k8.row.col.f32.tf32.tf32.f32 "
        "{%0,%1,%2,%3}, {%4,%5,%6,%7}, {%8,%9}, {%0,%1,%2,%3};\n"
        : "+f"(d[0]), "+f"(d[1]), "+f"(d[2]), "+f"(d[3])
        : "r"(a[0]), "r"(a[1]), "r"(a[2]), "r"(a[3]), "r"(b0), "r"(b1));
}

__device__ __forceinline__ void ldsm4(uint32_t* r, uint32_t saddr) {
    asm volatile(
        "ldmatrix.sync.aligned.m8n8.x4.shared.b16 {%0,%1,%2,%3}, [%4];\n"
        : "=r"(r[0]), "=r"(r[1]), "=r"(r[2]), "=r"(r[3]) : "r"(saddr));
}

// ---------------------------------------------------------------------------
// Kernel 1: reduce rel_pos_emb (2047,1024) -> table (2047,16), × log2(e)
// ---------------------------------------------------------------------------
__global__ __launch_bounds__(512) void reduce_table_kernel(const float* __restrict__ rel) {
    int row = blockIdx.x;
    int w   = threadIdx.x >> 5;
    int lane = threadIdx.x & 31;
    const float* p = rel + (size_t)row * C_ + w * D_;
    float s = p[lane] + p[lane + 32];
    #pragma unroll
    for (int off = 16; off > 0; off >>= 1)
        s += __shfl_xor_sync(0xffffffffu, s, off);
    if (lane == 0) g_table[row * H_ + w] = s * 1.4426950408889634f;
}

// ---------------------------------------------------------------------------
// Kernel 2: TF32 tensor-core GEMM (unchanged from R7)
// ---------------------------------------------------------------------------
#define TBM 128
#define TBN 128
#define TBK 16
#define GST 20
#define GBUF (TBM * GST)

__global__ __launch_bounds__(256, 2) void gemm_tf32_nt_bias(
    const float* __restrict__ A, const float* __restrict__ Bm,
    const float* __restrict__ bias, float* __restrict__ Cout,
    int M, int N, int K)
{
    __shared__ float As[2][TBM][GST];
    __shared__ float Bs[2][TBN][GST];

    const int tid  = threadIdx.x;
    const int lane = tid & 31;
    const int wid  = tid >> 5;
    const int wm   = (wid & 3) * 32;
    const int wn   = (wid >> 2) * 64;
    const int m0   = blockIdx.y * TBM;
    const int n0   = blockIdx.x * TBN;

    const int qr = lane >> 2;
    const int qc = lane & 3;

    const int lr = tid & 127;
    const int lh = tid >> 7;

    const float* Aptr = A  + (size_t)(m0 + lr) * K + lh * 8;
    const float* Bptr = Bm + (size_t)(n0 + lr) * K + lh * 8;

    const uint32_t baseA = (uint32_t)__cvta_generic_to_shared(&As[0][0][0]);
    const uint32_t baseB = (uint32_t)__cvta_generic_to_shared(&Bs[0][0][0]);
    const uint32_t aAddr = baseA + (((wm + (lane & 15)) * GST + (lane >> 4) * 4) << 2);
    uint32_t bAddr[4];
    #pragma unroll
    for (int g = 0; g < 4; g++)
        bAddr[g] = baseB + (((wn + 16 * g + (lane & 7) + ((lane >> 4) & 1) * 8) * GST
                             + ((lane >> 3) & 1) * 4) << 2);

    float acc[2][8][4];
    #pragma unroll
    for (int i = 0; i < 2; i++)
        #pragma unroll
        for (int j = 0; j < 8; j++)
            #pragma unroll
            for (int r = 0; r < 4; r++) acc[i][j][r] = 0.f;

    float4 fa[2], fb[2];
    #pragma unroll
    for (int j = 0; j < 2; j++) {
        fa[j] = *(const float4*)(Aptr + j * 4);
        fb[j] = *(const float4*)(Bptr + j * 4);
    }
    #pragma unroll
    for (int j = 0; j < 2; j++) {
        float* da = &As[0][lr][lh * 8 + j * 4];
        da[0] = tf32rf(fa[j].x); da[1] = tf32rf(fa[j].y);
        da[2] = tf32rf(fa[j].z); da[3] = tf32rf(fa[j].w);
        float* db = &Bs[0][lr][lh * 8 + j * 4];
        db[0] = tf32rf(fb[j].x); db[1] = tf32rf(fb[j].y);
        db[2] = tf32rf(fb[j].z); db[3] = tf32rf(fb[j].w);
    }
    __syncthreads();

    const int nIter = K / TBK;
    for (int t = 0; t < nIter; t++) {
        const int buf = t & 1;
        const uint32_t bo = (uint32_t)buf * (GBUF * 4);
        if (t + 1 < nIter) {
            const float* ap = Aptr + (t + 1) * TBK;
            const float* bp = Bptr + (t + 1) * TBK;
            #pragma unroll
            for (int j = 0; j < 2; j++) {
                fa[j] = *(const float4*)(ap + j * 4);
                fb[j] = *(const float4*)(bp + j * 4);
            }
        }

        #pragma unroll
        for (int ks = 0; ks < 2; ks++) {
            const uint32_t ko = bo + ks * 32;
            uint32_t af0[4], af1[4], bf[4][4];
            ldsm4(af0, aAddr + ko);
            ldsm4(af1, aAddr + (16 * GST * 4) + ko);
            #pragma unroll
            for (int g = 0; g < 4; g++) ldsm4(bf[g], bAddr[g] + ko);
            #pragma unroll
            for (int g = 0; g < 4; g++) {
                mma_tf32(acc[0][2 * g],     af0, bf[g][0], bf[g][1]);
                mma_tf32(acc[0][2 * g + 1], af0, bf[g][2], bf[g][3]);
                mma_tf32(acc[1][2 * g],     af1, bf[g][0], bf[g][1]);
                mma_tf32(acc[1][2 * g + 1], af1, bf[g][2], bf[g][3]);
            }
        }

        if (t + 1 < nIter) {
            const int nb = buf ^ 1;
            #pragma unroll
            for (int j = 0; j < 2; j++) {
                float* da = &As[nb][lr][lh * 8 + j * 4];
                da[0] = tf32rf(fa[j].x); da[1] = tf32rf(fa[j].y);
                da[2] = tf32rf(fa[j].z); da[3] = tf32rf(fa[j].w);
                float* db = &Bs[nb][lr][lh * 8 + j * 4];
                db[0] = tf32rf(fb[j].x); db[1] = tf32rf(fb[j].y);
                db[2] = tf32rf(fb[j].z); db[3] = tf32rf(fb[j].w);
            }
        }
        __syncthreads();
    }

    #pragma unroll
    for (int ms = 0; ms < 2; ms++) {
        int r = m0 + wm + ms * 16 + qr;
        #pragma unroll
        for (int ns = 0; ns < 8; ns++) {
            int c = n0 + wn + ns * 8 + qc * 2;
            float b0 = bias[c], b1 = bias[c + 1];
            float2 v0 = make_float2(acc[ms][ns][0] + b0, acc[ms][ns][1] + b1);
            float2 v1 = make_float2(acc[ms][ns][2] + b0, acc[ms][ns][3] + b1);
            *(float2*)&Cout[(size_t)r * N + c]       = v0;
            *(float2*)&Cout[(size_t)(r + 8) * N + c] = v1;
        }
    }
}

// ---------------------------------------------------------------------------
// Kernel 3: TF32 MMA flash attention v2 (ldmatrix everywhere, stride 68).
// Grid (T/128, B*H), 256 threads, 8 warps x 16 query rows, 64-key tiles.
// smem: Ks[64][68] | Vt[64][68] (V transposed) | QP[128][68] (Q, then P) | sb.
// Stride 68: 68/4=17 odd -> conflict-free ldmatrix rows and staging STS.
// ---------------------------------------------------------------------------
#define FST2 68
#define FOFF_KS 0
#define FOFF_VT (64 * FST2)
#define FOFF_QP (2 * 64 * FST2)
#define FOFF_SB (FOFF_QP + 128 * FST2)
#define FLASH2_FLOATS (FOFF_SB + 192)

__global__ __launch_bounds__(256, 2) void flash_mma2_kernel(float* __restrict__ out) {
    extern __shared__ float sm[];
    float* Ks = sm + FOFF_KS;   // [key][d]  stride 68
    float* Vt = sm + FOFF_VT;   // [d][key]  stride 68 (transposed V)
    float* QP = sm + FOFF_QP;   // [row][d] Q, later [row][key] P (per-warp slices)
    float* sb = sm + FOFF_SB;   // 191 bias values (log2 domain)

    const int bh = blockIdx.y;
    const int b  = bh >> 4;
    const int h  = bh & 15;
    const int m0 = blockIdx.x * 128;

    const int tid  = threadIdx.x;
    const int lane = tid & 31;
    const int wid  = tid >> 5;
    const int qr = lane >> 2;
    const int qc = lane & 3;
    const int wm = wid * 16;

    // stage Q (scaled by (1/8)*log2e, tf32-rounded)
    {
        const float qsc = 0.125f * 1.4426950408889634f;
        const float* qb = g_qkv + (size_t)(b * T_ + m0) * L3C + h * D_;
        #pragma unroll
        for (int i = 0; i < 8; i++) {
            int f = tid + i * 256;
            int row = f >> 4, c4 = (f & 15) * 4;
            float4 v = *(const float4*)(qb + (size_t)row * L3C + c4);
            float4 w = make_float4(tf32rf(v.x * qsc), tf32rf(v.y * qsc),
                                   tf32rf(v.z * qsc), tf32rf(v.w * qsc));
            *(float4*)&QP[row * FST2 + c4] = w;
        }
    }
    __syncthreads();

    // Q A-fragments into registers (loop-invariant); QP region then reused for P
    const uint32_t aAddr = (uint32_t)__cvta_generic_to_shared(QP)
        + (((wm + (lane & 15)) * FST2 + (lane >> 4) * 4) << 2);
    uint32_t qf[8][4];
    #pragma unroll
    for (int kb = 0; kb < 8; kb++) ldsm4(qf[kb], aAddr + kb * 32);

    // B-fragment lane addresses for K and Vt
    const uint32_t bRow = (lane & 7) + ((lane >> 4) & 1) * 8;
    const uint32_t bCol = ((lane >> 3) & 1) * 4;
    uint32_t kAddr[4], vAddr[4];
    {
        const uint32_t kBase = (uint32_t)__cvta_generic_to_shared(Ks);
        const uint32_t vBase = (uint32_t)__cvta_generic_to_shared(Vt);
        #pragma unroll
        for (int g = 0; g < 4; g++) {
            kAddr[g] = kBase + (((16 * g + bRow) * FST2 + bCol) << 2);
            vAddr[g] = vBase + (((16 * g + bRow) * FST2 + bCol) << 2);
        }
    }

    float m_i[2] = {-1e30f, -1e30f};
    float l_i[2] = {0.f, 0.f};
    float o[8][4];
    #pragma unroll
    for (int ns = 0; ns < 8; ns++)
        #pragma unroll
        for (int r = 0; r < 4; r++) o[ns][r] = 0.f;

    const float* kgb = g_qkv + (size_t)(b * T_) * L3C + C_ + h * D_;
    const float* vgb = kgb + C_;

    const int ntiles = 2 * blockIdx.x + 2;
    for (int t = 0; t < ntiles; t++) {
        const int j0 = t * 64;
        // stage K [key][d]
        #pragma unroll
        for (int i = 0; i < 4; i++) {
            int f = tid + i * 256;
            int row = f >> 4, c4 = (f & 15) * 4;
            float4 kv = *(const float4*)(kgb + (size_t)(j0 + row) * L3C + c4);
            float4 w = make_float4(tf32rf(kv.x), tf32rf(kv.y), tf32rf(kv.z), tf32rf(kv.w));
            *(float4*)&Ks[row * FST2 + c4] = w;
        }
        // stage V transposed: Vt[d][key] (coalesced gmem reads across d)
        {
            const int d  = tid & 63;
            const int kq = tid >> 6;
            #pragma unroll
            for (int c = 0; c < 4; c++) {
                int key4 = kq * 4 + c * 16;
                const float* vp = vgb + (size_t)(j0 + key4) * L3C + d;
                float4 w = make_float4(tf32rf(vp[0]),
                                       tf32rf(vp[(size_t)L3C]),
                                       tf32rf(vp[(size_t)2 * L3C]),
                                       tf32rf(vp[(size_t)3 * L3C]));
                *(float4*)&Vt[d * FST2 + key4] = w;
            }
        }
        if (tid < 191) sb[tid] = g_table[(m0 - j0 + 960 + tid) * H_ + h];
        __syncthreads();

        const int rel = j0 - m0;
        if (rel <= wm + 15) {   // warp not fully masked
            // S = Q @ K^T  (log2 domain)
            float sacc[8][4];
            #pragma unroll
            for (int ns = 0; ns < 8; ns++)
                #pragma unroll
                for (int r = 0; r < 4; r++) sacc[ns][r] = 0.f;

            #pragma unroll
            for (int kb = 0; kb < 8; kb++) {
                uint32_t bf[4][4];
                #pragma unroll
                for (int g = 0; g < 4; g++) ldsm4(bf[g], kAddr[g] + kb * 32);
                #pragma unroll
                for (int g = 0; g < 4; g++) {
                    mma_tf32(sacc[2 * g],     qf[kb], bf[g][0], bf[g][1]);
                    mma_tf32(sacc[2 * g + 1], qf[kb], bf[g][2], bf[g][3]);
                }
            }

            // bias + causal mask + online softmax
            const bool tail = (rel >= 0);
            #pragma unroll
            for (int hl = 0; hl < 2; hl++) {
                const int rloc = wm + qr + hl * 8;
                float mx = -1e30f;
                #pragma unroll
                for (int ns = 0; ns < 8; ns++) {
                    #pragma unroll
                    for (int j2 = 0; j2 < 2; j2++) {
                        int col = ns * 8 + qc * 2 + j2;
                        float v = sacc[ns][hl * 2 + j2] + sb[rloc - col + 63];
                        if (tail && col + rel > rloc) v = -1e30f;
                        sacc[ns][hl * 2 + j2] = v;
                        mx = fmaxf(mx, v);
                    }
                }
                mx = fmaxf(mx, __shfl_xor_sync(0xffffffffu, mx, 1));
                mx = fmaxf(mx, __shfl_xor_sync(0xffffffffu, mx, 2));
                float mnew = fmaxf(m_i[hl], mx);
                float corr = ex2f(m_i[hl] - mnew);
                float rs = 0.f;
                #pragma unroll
                for (int ns = 0; ns < 8; ns++) {
                    #pragma unroll
                    for (int j2 = 0; j2 < 2; j2++) {
                        float p = ex2f(sacc[ns][hl * 2 + j2] - mnew);
                        sacc[ns][hl * 2 + j2] = p;
                        rs += p;
                    }
                }
                rs += __shfl_xor_sync(0xffffffffu, rs, 1);
                rs += __shfl_xor_sync(0xffffffffu, rs, 2);
                l_i[hl] = l_i[hl] * corr + rs;
                m_i[hl] = mnew;
                #pragma unroll
                for (int ns = 0; ns < 8; ns++) {
                    o[ns][hl * 2 + 0] *= corr;
                    o[ns][hl * 2 + 1] *= corr;
                }
            }

            // stage P (tf32) into this warp's own 16-row slice of QP
            {
                float* Pw = QP + wm * FST2;
                #pragma unroll
                for (int ns = 0; ns < 8; ns++) {
                    float2 p0 = make_float2(tf32rf(sacc[ns][0]), tf32rf(sacc[ns][1]));
                    float2 p1 = make_float2(tf32rf(sacc[ns][2]), tf32rf(sacc[ns][3]));
                    *(float2*)&Pw[qr * FST2 + ns * 8 + qc * 2] = p0;
                    *(float2*)&Pw[(qr + 8) * FST2 + ns * 8 + qc * 2] = p1;
                }
            }
            __syncwarp();

            // O += P @ V   (A-frags from P slice, B-frags from Vt)
            #pragma unroll
            for (int kb = 0; kb < 8; kb++) {
                uint32_t pa[4];
                ldsm4(pa, aAddr + kb * 32);
                uint32_t bf[4][4];
                #pragma unroll
                for (int g = 0; g < 4; g++) ldsm4(bf[g], vAddr[g] + kb * 32);
                #pragma unroll
                for (int g = 0; g < 4; g++) {
                    mma_tf32(o[2 * g],     pa, bf[g][0], bf[g][1]);
                    mma_tf32(o[2 * g + 1], pa, bf[g][2], bf[g][3]);
                }
            }
        }
        __syncthreads();
    }

    // epilogue: normalize, write (B,T,H*D)
    #pragma unroll
    for (int hl = 0; hl < 2; hl++) {
        float inv = 1.f / l_i[hl];
        int rg = m0 + wm + qr + hl * 8;
        float* ob = out + (size_t)(b * T_ + rg) * C_ + h * D_;
        #pragma unroll
        for (int ns = 0; ns < 8; ns++) {
            float2 w = make_float2(o[ns][hl * 2 + 0] * inv, o[ns][hl * 2 + 1] * inv);
            *(float2*)&ob[ns * 8 + qc * 2] = w;
        }
    }
}

// ---------------------------------------------------------------------------
extern "C" void kernel_launch(void* const* d_in, const int* in_sizes, int n_in,
                              void* d_out, int out_size) {
    const float* x      = (const float*)d_in[0];
    const float* qkv_w  = (const float*)d_in[1];
    const float* qkv_b  = (const float*)d_in[2];
    const float* proj_w = (const float*)d_in[3];
    const float* proj_b = (const float*)d_in[4];
    const float* rel    = (const float*)d_in[5];
    float* out = (float*)d_out;

    float *p_qkv, *p_attn;
    cudaGetSymbolAddress((void**)&p_qkv, g_qkv);
    cudaGetSymbolAddress((void**)&p_attn, g_attn);

    // 1) bias table reduce (log2 domain)
    reduce_table_kernel<<<NPOS, 512>>>(rel);

    // 2) QKV projection (tf32 MMA + ldmatrix)
    {
        dim3 grid(L3C / TBN, (B_ * T_) / TBM);
        gemm_tf32_nt_bias<<<grid, 256>>>(x, qkv_w, qkv_b, p_qkv, B_ * T_, L3C, C_);
    }

    // 3) fused flash attention (tf32 MMA + ldmatrix)
    {
        static int smem_set = 0;
        size_t smem = FLASH2_FLOATS * sizeof(float);
        if (!smem_set) {
            cudaFuncSetAttribute(flash_mma2_kernel,
                                 cudaFuncAttributeMaxDynamicSharedMemorySize, (int)smem);
            smem_set = 1;
        }
        dim3 grid(T_ / 128, B_ * H_);
        flash_mma2_kernel<<<grid, 256, smem>>>(p_attn);
    }

    // 4) output projection (tf32 MMA + ldmatrix)
    {
        dim3 grid(C_ / TBN, (B_ * T_) / TBM);
        gemm_tf32_nt_bias<<<grid, 256>>>(p_attn, proj_w, proj_b, out, B_ * T_, C_, C_);
    }
}